// round 6
// baseline (speedup 1.0000x reference)
#include <cuda_runtime.h>
#include <math.h>
#include <stdint.h>

#define NIMG   8
#define KSEL   4768
#define NWORDS 75          /* ceil(4768/64) */
#define POSTN  1000

typedef unsigned long long u64;
typedef unsigned int u32;

__device__ __constant__ int c_FEAT[5]   = {256, 128, 64, 32, 16};
__device__ __constant__ int c_KLVL[5]   = {1000, 1000, 1000, 1000, 768};
__device__ __constant__ int c_SELOFF[5] = {0, 1000, 2000, 3000, 4000};
__device__ __constant__ int c_LOFF[5]   = {0, 196608, 245760, 258048, 261120};

struct KArgs {
    const float* obj[5];
    const float* del[5];
    const float* anc;
};

// ------------- static device scratch (no allocation) -------------
__device__ u32   g_selIdx[NIMG][KSEL];        // concat-pos -> global anchor index
__device__ u64   g_keyB[NIMG][8192];          // global per-image sort keys
__device__ float4 g_px[NIMG][KSEL];           // pos-indexed clipped boxes
__device__ float g_sx1[NIMG][KSEL], g_sy1[NIMG][KSEL], g_sx2[NIMG][KSEL], g_sy2[NIMG][KSEL];
__device__ float g_ox1[NIMG][KSEL], g_oy1[NIMG][KSEL], g_ox2[NIMG][KSEL], g_oy2[NIMG][KSEL];
__device__ float g_area[NIMG][KSEL];
__device__ unsigned char g_valid[NIMG][KSEL];
__device__ u64   g_mask[NIMG][KSEL][NWORDS];  // suppression bit matrix

// monotone float->uint key (ascending float == ascending uint)
__device__ __forceinline__ u32 fkey(float f) {
    u32 b = __float_as_uint(f);
    return (b & 0x80000000u) ? ~b : (b | 0x80000000u);
}

// ================= kernel 1: per-(img,level) exact top-k =================
__global__ __launch_bounds__(1024) void sel_kernel(KArgs A) {
    int img = blockIdx.x / 5, lvl = blockIdx.x % 5;
    const float* obj = A.obj[lvl];
    int F = c_FEAT[lvl]; int HW = F * F; int n = HW * 3; int k = c_KLVL[lvl];
    const float* base = obj + (size_t)img * 3 * HW;

    __shared__ u32 hist[256];
    __shared__ u32 sh_prefix, sh_kr;
    __shared__ u64 buf[2048];
    __shared__ u32 cntG, cntE;

    if (threadIdx.x == 0) { sh_prefix = 0; sh_kr = (u32)k; }
    __syncthreads();

    // 4-pass MSB radix select for the exact k-th largest key
    for (int b = 3; b >= 0; b--) {
        for (int t = threadIdx.x; t < 256; t += blockDim.x) hist[t] = 0;
        __syncthreads();
        u32 pref = sh_prefix;
        u32 maskH = (b == 3) ? 0u : (0xFFFFFFFFu << (8 * (b + 1)));
        for (int t = threadIdx.x; t < n; t += blockDim.x) {
            u32 key = fkey(base[t]);
            if ((key & maskH) == (pref & maskH))
                atomicAdd(&hist[(key >> (8 * b)) & 255u], 1u);
        }
        __syncthreads();
        if (threadIdx.x == 0) {
            u32 kr = sh_kr, sum = 0; int d = 0;
            for (d = 255; d >= 0; d--) {
                u32 s2 = sum + hist[d];
                if (s2 >= kr) { sh_kr = kr - sum; break; }
                sum = s2;
            }
            sh_prefix = pref | ((u32)d << (8 * b));
        }
        __syncthreads();
    }
    u32 Kth = sh_prefix;

    // compact: strictly-greater into [0,1000), equals into [1000,2048)
    if (threadIdx.x == 0) { cntG = 0; cntE = 0; }
    for (int t = threadIdx.x; t < 2048; t += blockDim.x) buf[t] = 0ull;
    __syncthreads();
    for (int t = threadIdx.x; t < n; t += blockDim.x) {
        u32 key = fkey(base[t]);
        if (key >= Kth) {
            int a = t / HW; int hw = t - a * HW;
            u32 local = (u32)hw * 3u + (u32)a;     // [H,W,A] flatten index
            u64 comp = ((u64)key << 32) | (u32)(~local);
            if (key > Kth) { u32 s = atomicAdd(&cntG, 1u); if (s < 1000u) buf[s] = comp; }
            else           { u32 s = atomicAdd(&cntE, 1u); if (s < 1048u) buf[1000u + s] = comp; }
        }
    }
    __syncthreads();

    // bitonic sort 2048 descending on (key desc, local asc)
    for (int kk = 2; kk <= 2048; kk <<= 1)
        for (int j = kk >> 1; j > 0; j >>= 1) {
            __syncthreads();
            for (int t = threadIdx.x; t < 2048; t += blockDim.x) {
                int ixj = t ^ j;
                if (ixj > t) {
                    u64 a = buf[t], bb = buf[ixj];
                    bool desc = ((t & kk) == 0);
                    if (desc ? (a < bb) : (a > bb)) { buf[t] = bb; buf[ixj] = a; }
                }
            }
        }
    __syncthreads();

    int seloff = c_SELOFF[lvl], loff = c_LOFF[lvl];
    for (int r = threadIdx.x; r < k; r += blockDim.x) {
        u32 local = ~(u32)buf[r];
        g_selIdx[img][seloff + r] = (u32)loff + local;
    }
}

// ================= kernel 2: decode + score + global sort key =================
__global__ void stage2_kernel(KArgs A) {
    int img = blockIdx.y;
    int pos = blockIdx.x * blockDim.x + threadIdx.x;
    if (pos >= KSEL) return;
    int lvl = pos / 1000; if (lvl > 4) lvl = 4;
    u32 gidx = g_selIdx[img][pos];
    int loff = c_LOFF[lvl]; int F = c_FEAT[lvl]; int HW = F * F;
    u32 local = gidx - (u32)loff;
    int a = (int)(local % 3u); int hw = (int)(local / 3u);
    int h = hw / F; int w = hw - h * F;

    float logit = A.obj[lvl][((size_t)img * 3 + a) * HW + hw];
    float score = __fdiv_rn(1.0f, __fadd_rn(1.0f, expf(-logit)));

    const float* dp = A.del[lvl] + ((size_t)img * 12 + a * 4) * HW + (size_t)h * F + w;
    float dx  = dp[0];
    float dy  = dp[(size_t)HW];
    float dwv = dp[2 * (size_t)HW];
    float dhv = dp[3 * (size_t)HW];
    const float* an = A.anc + 4 * (size_t)gidx;
    float ax1 = an[0], ay1 = an[1], ax2 = an[2], ay2 = an[3];
    float aw = __fsub_rn(ax2, ax1);
    float ah = __fsub_rn(ay2, ay1);
    float cx = __fadd_rn(ax1, __fmul_rn(0.5f, aw));
    float cy = __fadd_rn(ay1, __fmul_rn(0.5f, ah));
    const float CLIP = 4.135166556742356f;
    float dwc = fminf(dwv, CLIP);
    float dhc = fminf(dhv, CLIP);
    float pcx = __fadd_rn(__fmul_rn(dx, aw), cx);
    float pcy = __fadd_rn(__fmul_rn(dy, ah), cy);
    float pw  = __fmul_rn(expf(dwc), aw);
    float ph  = __fmul_rn(expf(dhc), ah);
    float x1 = __fsub_rn(pcx, __fmul_rn(0.5f, pw));
    float y1 = __fsub_rn(pcy, __fmul_rn(0.5f, ph));
    float x2 = __fadd_rn(pcx, __fmul_rn(0.5f, pw));
    float y2 = __fadd_rn(pcy, __fmul_rn(0.5f, ph));
    x1 = fminf(fmaxf(x1, 0.0f), 1024.0f);
    y1 = fminf(fmaxf(y1, 0.0f), 1024.0f);
    x2 = fminf(fmaxf(x2, 0.0f), 1024.0f);
    y2 = fminf(fmaxf(y2, 0.0f), 1024.0f);

    bool valid = (__fsub_rn(x2, x1) >= 1e-3f) && (__fsub_rn(y2, y1) >= 1e-3f);
    float s = valid ? score : -1.0f;
    g_keyB[img][pos] = ((u64)fkey(s) << 32) | (u32)(~(u32)pos);
    g_px[img][pos] = make_float4(x1, y1, x2, y2);
}

// ================= kernel 3: per-image 8192 bitonic sort =================
extern __shared__ u64 sk[];
__global__ __launch_bounds__(1024) void sortB_kernel() {
    int img = blockIdx.x;
    for (int t = threadIdx.x; t < 8192; t += 1024)
        sk[t] = (t < KSEL) ? g_keyB[img][t] : 0ull;
    for (int kk = 2; kk <= 8192; kk <<= 1)
        for (int j = kk >> 1; j > 0; j >>= 1) {
            __syncthreads();
            for (int t = threadIdx.x; t < 8192; t += 1024) {
                int ixj = t ^ j;
                if (ixj > t) {
                    u64 a = sk[t], b = sk[ixj];
                    bool desc = ((t & kk) == 0);
                    if (desc ? (a < b) : (a > b)) { sk[t] = b; sk[ixj] = a; }
                }
            }
        }
    __syncthreads();
    for (int t = threadIdx.x; t < KSEL; t += 1024) g_keyB[img][t] = sk[t];
}

// ================= kernel 4: gather sorted SoA =================
__global__ void stage3_kernel() {
    int img = blockIdx.y;
    int t = blockIdx.x * blockDim.x + threadIdx.x;
    if (t >= KSEL) return;
    u64 key = g_keyB[img][t];
    u32 pos = ~(u32)key;
    int lvl = (int)(pos / 1000u); if (lvl > 4) lvl = 4;
    float4 b = g_px[img][pos];
    g_sx1[img][t] = b.x; g_sy1[img][t] = b.y; g_sx2[img][t] = b.z; g_sy2[img][t] = b.w;
    float ofs = (float)lvl * 1025.0f;
    float ox1 = __fadd_rn(b.x, ofs), oy1 = __fadd_rn(b.y, ofs);
    float ox2 = __fadd_rn(b.z, ofs), oy2 = __fadd_rn(b.w, ofs);
    g_ox1[img][t] = ox1; g_oy1[img][t] = oy1; g_ox2[img][t] = ox2; g_oy2[img][t] = oy2;
    g_area[img][t] = __fmul_rn(__fsub_rn(ox2, ox1), __fsub_rn(oy2, oy1));
    g_valid[img][t] = (__fsub_rn(b.z, b.x) >= 1e-3f) && (__fsub_rn(b.w, b.y) >= 1e-3f);
}

// ================= kernel 5: IoU suppression mask matrix =================
__global__ __launch_bounds__(64) void mask_kernel() {
    int colb = blockIdx.x, rowb = blockIdx.y, img = blockIdx.z;
    int i = rowb * 64 + threadIdx.x;
    if (colb < rowb) {                     // j <= colb*64+63 < rowb*64 <= i → all bits 0
        if (i < KSEL) g_mask[img][i][colb] = 0ull;
        return;
    }
    __shared__ float cx1[64], cy1[64], cx2[64], cy2[64], car[64];
    int j0 = colb * 64;
    int tj = j0 + threadIdx.x;
    if (tj < KSEL) {
        cx1[threadIdx.x] = g_ox1[img][tj]; cy1[threadIdx.x] = g_oy1[img][tj];
        cx2[threadIdx.x] = g_ox2[img][tj]; cy2[threadIdx.x] = g_oy2[img][tj];
        car[threadIdx.x] = g_area[img][tj];
    } else {
        cx1[threadIdx.x] = 0.f; cy1[threadIdx.x] = 0.f;
        cx2[threadIdx.x] = 0.f; cy2[threadIdx.x] = 0.f; car[threadIdx.x] = 0.f;
    }
    __syncthreads();
    if (i >= KSEL) return;
    float ix1 = g_ox1[img][i], iy1 = g_oy1[img][i];
    float ix2 = g_ox2[img][i], iy2 = g_oy2[img][i];
    float ai = g_area[img][i];
    u64 word = 0ull;
    #pragma unroll 4
    for (int jj = 0; jj < 64; jj++) {
        int j = j0 + jj;
        if (j < KSEL && j > i) {
            float ltx = fmaxf(ix1, cx1[jj]);
            float lty = fmaxf(iy1, cy1[jj]);
            float rbx = fminf(ix2, cx2[jj]);
            float rby = fminf(iy2, cy2[jj]);
            float w = fmaxf(__fsub_rn(rbx, ltx), 0.0f);
            float h = fmaxf(__fsub_rn(rby, lty), 0.0f);
            float inter = __fmul_rn(w, h);
            float den = __fadd_rn(__fsub_rn(__fadd_rn(ai, car[jj]), inter), 1e-9f);
            if (__fdiv_rn(inter, den) > 0.7f) word |= (1ull << jj);
        }
    }
    g_mask[img][i][colb] = word;
}

// ================= kernel 6: sequential greedy NMS scan + output =================
__global__ __launch_bounds__(128) void nms_scan_kernel(float* __restrict__ out) {
    int img = blockIdx.x;
    __shared__ u64 remv[NWORDS];
    __shared__ u64 smask[64];
    __shared__ unsigned char sval[64];
    __shared__ int skept[64];
    __shared__ int snk, skbase;
    for (int t = threadIdx.x; t < NWORDS; t += blockDim.x) remv[t] = 0ull;
    if (threadIdx.x == 0) { skbase = 0; snk = 0; }
    __syncthreads();

    for (int c = 0; c < NWORDS; c++) {
        if (skbase >= POSTN) break;     // uniform (shared, synced)
        int i0 = c * 64;
        for (int t = threadIdx.x; t < 64; t += blockDim.x) {
            int i = i0 + t;
            smask[t] = (i < KSEL) ? g_mask[img][i][c] : 0ull;
            sval[t]  = (i < KSEL) ? g_valid[img][i] : (unsigned char)0;
        }
        __syncthreads();
        if (threadIdx.x == 0) {
            u64 cur = remv[c];
            int nk = 0;
            int lim = KSEL - i0; if (lim > 64) lim = 64;
            for (int b = 0; b < lim; b++) {
                if (sval[b] && !((cur >> b) & 1ull)) {
                    skept[nk++] = i0 + b;
                    cur |= smask[b];
                }
            }
            snk = nk;
        }
        __syncthreads();
        int nk = snk, kbase = skbase;
        for (int kk = threadIdx.x; kk < nk; kk += blockDim.x) {
            int rank = kbase + kk;
            if (rank < POSTN) {
                int i = skept[kk];
                float* o = out + ((size_t)img * POSTN + rank) * 4;
                o[0] = g_sx1[img][i]; o[1] = g_sy1[img][i];
                o[2] = g_sx2[img][i]; o[3] = g_sy2[img][i];
            }
        }
        for (int t = threadIdx.x; t < NWORDS; t += blockDim.x) {
            u64 v = remv[t];
            for (int kk = 0; kk < nk; kk++) v |= g_mask[img][skept[kk]][t];
            remv[t] = v;
        }
        __syncthreads();
        if (threadIdx.x == 0) skbase = kbase + nk;
        __syncthreads();
    }
    __syncthreads();
    int tot = skbase; if (tot > POSTN) tot = POSTN;
    for (int idx = tot * 4 + threadIdx.x; idx < POSTN * 4; idx += blockDim.x)
        out[(size_t)img * POSTN * 4 + idx] = 0.0f;
}

// ================= host launcher =================
extern "C" void kernel_launch(void* const* d_in, const int* in_sizes, int n_in,
                              void* d_out, int out_size) {
    KArgs A;
    // detect input ordering: interleaved (obj_l0,delta_l0,...) vs grouped (obj_l0..4,delta_l0..4)
    bool interleaved = (in_sizes[1] == 6291456);
    for (int i = 0; i < 5; i++) {
        A.obj[i] = (const float*)d_in[interleaved ? 2 * i : i];
        A.del[i] = (const float*)d_in[interleaved ? 2 * i + 1 : 5 + i];
    }
    A.anc = (const float*)d_in[10];
    float* out = (float*)d_out;

    cudaFuncSetAttribute(sortB_kernel, cudaFuncAttributeMaxDynamicSharedMemorySize, 65536);

    sel_kernel<<<40, 1024>>>(A);
    stage2_kernel<<<dim3(19, NIMG), 256>>>(A);
    sortB_kernel<<<NIMG, 1024, 65536>>>();
    stage3_kernel<<<dim3(19, NIMG), 256>>>();
    mask_kernel<<<dim3(NWORDS, NWORDS, NIMG), 64>>>();
    nms_scan_kernel<<<NIMG, 128>>>(out);
}

// round 7
// speedup vs baseline: 1.1395x; 1.1395x over previous
#include <cuda_runtime.h>
#include <math.h>
#include <stdint.h>

#define NIMG   8
#define KSEL   4768
#define NWORDS 75          /* ceil(4768/64) */
#define POSTN  1000

typedef unsigned long long u64;
typedef unsigned int u32;

__device__ __constant__ int c_FEAT[5]   = {256, 128, 64, 32, 16};
__device__ __constant__ int c_KLVL[5]   = {1000, 1000, 1000, 1000, 768};
__device__ __constant__ int c_SELOFF[5] = {0, 1000, 2000, 3000, 4000};
__device__ __constant__ int c_LOFF[5]   = {0, 196608, 245760, 258048, 261120};

struct KArgs {
    const float* obj[5];
    const float* del[5];
    const float* anc;
};

// ------------- static device scratch (no allocation) -------------
__device__ u32   g_selIdx[NIMG][KSEL];        // concat-pos -> global anchor index
__device__ u64   g_keyB[NIMG][8192];          // global per-image sort keys
__device__ float4 g_px[NIMG][KSEL];           // pos-indexed clipped boxes
__device__ float g_sx1[NIMG][KSEL], g_sy1[NIMG][KSEL], g_sx2[NIMG][KSEL], g_sy2[NIMG][KSEL];
__device__ float g_ox1[NIMG][KSEL], g_oy1[NIMG][KSEL], g_ox2[NIMG][KSEL], g_oy2[NIMG][KSEL];
__device__ float g_area[NIMG][KSEL];
__device__ u64   g_vbits[NIMG][NWORDS];       // per-chunk valid bitmask (rank order)
__device__ u64   g_mask[NIMG][KSEL][NWORDS];  // suppression bit matrix (upper tri only)

// monotone float->uint key (ascending float == ascending uint)
__device__ __forceinline__ u32 fkey(float f) {
    u32 b = __float_as_uint(f);
    return (b & 0x80000000u) ? ~b : (b | 0x80000000u);
}

// ================= kernel 1: per-(img,level) exact top-k =================
__global__ __launch_bounds__(1024) void sel_kernel(KArgs A) {
    int img = blockIdx.x / 5, lvl = blockIdx.x % 5;
    const float* obj = A.obj[lvl];
    int F = c_FEAT[lvl]; int HW = F * F; int n = HW * 3; int k = c_KLVL[lvl];
    const float* base = obj + (size_t)img * 3 * HW;

    __shared__ u32 hist[256];
    __shared__ u32 sh_prefix, sh_kr;
    __shared__ u64 buf[2048];
    __shared__ u32 cntG, cntE;

    if (threadIdx.x == 0) { sh_prefix = 0; sh_kr = (u32)k; }
    __syncthreads();

    // 4-pass MSB radix select for the exact k-th largest key
    for (int b = 3; b >= 0; b--) {
        for (int t = threadIdx.x; t < 256; t += blockDim.x) hist[t] = 0;
        __syncthreads();
        u32 pref = sh_prefix;
        u32 maskH = (b == 3) ? 0u : (0xFFFFFFFFu << (8 * (b + 1)));
        for (int t = threadIdx.x; t < n; t += blockDim.x) {
            u32 key = fkey(base[t]);
            if ((key & maskH) == (pref & maskH))
                atomicAdd(&hist[(key >> (8 * b)) & 255u], 1u);
        }
        __syncthreads();
        if (threadIdx.x == 0) {
            u32 kr = sh_kr, sum = 0; int d = 0;
            for (d = 255; d >= 0; d--) {
                u32 s2 = sum + hist[d];
                if (s2 >= kr) { sh_kr = kr - sum; break; }
                sum = s2;
            }
            sh_prefix = pref | ((u32)d << (8 * b));
        }
        __syncthreads();
    }
    u32 Kth = sh_prefix;

    // compact: strictly-greater into [0,1000), equals into [1000,2048)
    if (threadIdx.x == 0) { cntG = 0; cntE = 0; }
    for (int t = threadIdx.x; t < 2048; t += blockDim.x) buf[t] = 0ull;
    __syncthreads();
    for (int t = threadIdx.x; t < n; t += blockDim.x) {
        u32 key = fkey(base[t]);
        if (key >= Kth) {
            int a = t / HW; int hw = t - a * HW;
            u32 local = (u32)hw * 3u + (u32)a;     // [H,W,A] flatten index
            u64 comp = ((u64)key << 32) | (u32)(~local);
            if (key > Kth) { u32 s = atomicAdd(&cntG, 1u); if (s < 1000u) buf[s] = comp; }
            else           { u32 s = atomicAdd(&cntE, 1u); if (s < 1048u) buf[1000u + s] = comp; }
        }
    }
    __syncthreads();

    // bitonic sort 2048 descending on (key desc, local asc)
    for (int kk = 2; kk <= 2048; kk <<= 1)
        for (int j = kk >> 1; j > 0; j >>= 1) {
            __syncthreads();
            for (int t = threadIdx.x; t < 2048; t += blockDim.x) {
                int ixj = t ^ j;
                if (ixj > t) {
                    u64 a = buf[t], bb = buf[ixj];
                    bool desc = ((t & kk) == 0);
                    if (desc ? (a < bb) : (a > bb)) { buf[t] = bb; buf[ixj] = a; }
                }
            }
        }
    __syncthreads();

    int seloff = c_SELOFF[lvl], loff = c_LOFF[lvl];
    for (int r = threadIdx.x; r < k; r += blockDim.x) {
        u32 local = ~(u32)buf[r];
        g_selIdx[img][seloff + r] = (u32)loff + local;
    }
}

// ================= kernel 2: decode + score + global sort key =================
__global__ void stage2_kernel(KArgs A) {
    int img = blockIdx.y;
    int pos = blockIdx.x * blockDim.x + threadIdx.x;
    if (pos < NWORDS) g_vbits[img][pos] = 0ull;   // reset valid bitmask each run
    if (pos >= KSEL) return;
    int lvl = pos / 1000; if (lvl > 4) lvl = 4;
    u32 gidx = g_selIdx[img][pos];
    int loff = c_LOFF[lvl]; int F = c_FEAT[lvl]; int HW = F * F;
    u32 local = gidx - (u32)loff;
    int a = (int)(local % 3u); int hw = (int)(local / 3u);
    int h = hw / F; int w = hw - h * F;

    float logit = A.obj[lvl][((size_t)img * 3 + a) * HW + hw];
    float score = __fdiv_rn(1.0f, __fadd_rn(1.0f, expf(-logit)));

    const float* dp = A.del[lvl] + ((size_t)img * 12 + a * 4) * HW + (size_t)h * F + w;
    float dx  = dp[0];
    float dy  = dp[(size_t)HW];
    float dwv = dp[2 * (size_t)HW];
    float dhv = dp[3 * (size_t)HW];
    const float* an = A.anc + 4 * (size_t)gidx;
    float ax1 = an[0], ay1 = an[1], ax2 = an[2], ay2 = an[3];
    float aw = __fsub_rn(ax2, ax1);
    float ah = __fsub_rn(ay2, ay1);
    float cx = __fadd_rn(ax1, __fmul_rn(0.5f, aw));
    float cy = __fadd_rn(ay1, __fmul_rn(0.5f, ah));
    const float CLIP = 4.135166556742356f;
    float dwc = fminf(dwv, CLIP);
    float dhc = fminf(dhv, CLIP);
    float pcx = __fadd_rn(__fmul_rn(dx, aw), cx);
    float pcy = __fadd_rn(__fmul_rn(dy, ah), cy);
    float pw  = __fmul_rn(expf(dwc), aw);
    float ph  = __fmul_rn(expf(dhc), ah);
    float x1 = __fsub_rn(pcx, __fmul_rn(0.5f, pw));
    float y1 = __fsub_rn(pcy, __fmul_rn(0.5f, ph));
    float x2 = __fadd_rn(pcx, __fmul_rn(0.5f, pw));
    float y2 = __fadd_rn(pcy, __fmul_rn(0.5f, ph));
    x1 = fminf(fmaxf(x1, 0.0f), 1024.0f);
    y1 = fminf(fmaxf(y1, 0.0f), 1024.0f);
    x2 = fminf(fmaxf(x2, 0.0f), 1024.0f);
    y2 = fminf(fmaxf(y2, 0.0f), 1024.0f);

    bool valid = (__fsub_rn(x2, x1) >= 1e-3f) && (__fsub_rn(y2, y1) >= 1e-3f);
    float s = valid ? score : -1.0f;
    g_keyB[img][pos] = ((u64)fkey(s) << 32) | (u32)(~(u32)pos);
    g_px[img][pos] = make_float4(x1, y1, x2, y2);
}

// ================= kernel 3: per-image 8192 bitonic sort =================
extern __shared__ u64 sk[];
__global__ __launch_bounds__(1024) void sortB_kernel() {
    int img = blockIdx.x;
    for (int t = threadIdx.x; t < 8192; t += 1024)
        sk[t] = (t < KSEL) ? g_keyB[img][t] : 0ull;
    for (int kk = 2; kk <= 8192; kk <<= 1)
        for (int j = kk >> 1; j > 0; j >>= 1) {
            __syncthreads();
            for (int t = threadIdx.x; t < 8192; t += 1024) {
                int ixj = t ^ j;
                if (ixj > t) {
                    u64 a = sk[t], b = sk[ixj];
                    bool desc = ((t & kk) == 0);
                    if (desc ? (a < b) : (a > b)) { sk[t] = b; sk[ixj] = a; }
                }
            }
        }
    __syncthreads();
    for (int t = threadIdx.x; t < KSEL; t += 1024) g_keyB[img][t] = sk[t];
}

// ================= kernel 4: gather sorted SoA + valid bitmask =================
__global__ void stage3_kernel() {
    int img = blockIdx.y;
    int t = blockIdx.x * blockDim.x + threadIdx.x;
    if (t >= KSEL) return;
    u64 key = g_keyB[img][t];
    u32 pos = ~(u32)key;
    int lvl = (int)(pos / 1000u); if (lvl > 4) lvl = 4;
    float4 b = g_px[img][pos];
    g_sx1[img][t] = b.x; g_sy1[img][t] = b.y; g_sx2[img][t] = b.z; g_sy2[img][t] = b.w;
    float ofs = (float)lvl * 1025.0f;
    float ox1 = __fadd_rn(b.x, ofs), oy1 = __fadd_rn(b.y, ofs);
    float ox2 = __fadd_rn(b.z, ofs), oy2 = __fadd_rn(b.w, ofs);
    g_ox1[img][t] = ox1; g_oy1[img][t] = oy1; g_ox2[img][t] = ox2; g_oy2[img][t] = oy2;
    g_area[img][t] = __fmul_rn(__fsub_rn(ox2, ox1), __fsub_rn(oy2, oy1));
    bool valid = (__fsub_rn(b.z, b.x) >= 1e-3f) && (__fsub_rn(b.w, b.y) >= 1e-3f);
    if (valid) atomicOr(&g_vbits[img][t >> 6], 1ull << (t & 63));
}

// ================= kernel 5: IoU suppression mask matrix (upper tri) =================
__global__ __launch_bounds__(64) void mask_kernel() {
    int colb = blockIdx.x, rowb = blockIdx.y, img = blockIdx.z;
    if (colb < rowb) return;               // lower-triangle words are never read
    int i = rowb * 64 + threadIdx.x;
    __shared__ float cx1[64], cy1[64], cx2[64], cy2[64], car[64];
    int j0 = colb * 64;
    int tj = j0 + threadIdx.x;
    if (tj < KSEL) {
        cx1[threadIdx.x] = g_ox1[img][tj]; cy1[threadIdx.x] = g_oy1[img][tj];
        cx2[threadIdx.x] = g_ox2[img][tj]; cy2[threadIdx.x] = g_oy2[img][tj];
        car[threadIdx.x] = g_area[img][tj];
    } else {
        cx1[threadIdx.x] = 0.f; cy1[threadIdx.x] = 0.f;
        cx2[threadIdx.x] = 0.f; cy2[threadIdx.x] = 0.f; car[threadIdx.x] = 0.f;
    }
    __syncthreads();
    if (i >= KSEL) return;
    float ix1 = g_ox1[img][i], iy1 = g_oy1[img][i];
    float ix2 = g_ox2[img][i], iy2 = g_oy2[img][i];
    float ai = g_area[img][i];
    u64 word = 0ull;
    #pragma unroll 4
    for (int jj = 0; jj < 64; jj++) {
        int j = j0 + jj;
        if (j < KSEL && j > i) {
            float ltx = fmaxf(ix1, cx1[jj]);
            float lty = fmaxf(iy1, cy1[jj]);
            float rbx = fminf(ix2, cx2[jj]);
            float rby = fminf(iy2, cy2[jj]);
            float w = fmaxf(__fsub_rn(rbx, ltx), 0.0f);
            float h = fmaxf(__fsub_rn(rby, lty), 0.0f);
            float inter = __fmul_rn(w, h);
            float den = __fadd_rn(__fsub_rn(__fadd_rn(ai, car[jj]), inter), 1e-9f);
            if (__fdiv_rn(inter, den) > 0.7f) word |= (1ull << jj);
        }
    }
    g_mask[img][i][colb] = word;
}

// ================= kernel 6: greedy NMS scan (parallel remv update) =================
__global__ __launch_bounds__(1024) void nms_scan_kernel(float* __restrict__ out) {
    int img = blockIdx.x;
    __shared__ u64 remv[NWORDS];
    __shared__ u64 smaskc[64];
    __shared__ int skept[64];
    __shared__ int snk, skbase;
    for (int t = threadIdx.x; t < NWORDS; t += blockDim.x) remv[t] = 0ull;
    if (threadIdx.x == 0) { skbase = 0; snk = 0; }
    __syncthreads();

    for (int c = 0; c < NWORDS; c++) {
        if (skbase >= POSTN) break;          // uniform: shared + synced
        int i0 = c * 64;
        if (threadIdx.x < 64) {
            int i = i0 + threadIdx.x;
            smaskc[threadIdx.x] = (i < KSEL) ? g_mask[img][i][c] : 0ull;
        }
        __syncthreads();
        if (threadIdx.x == 0) {
            u64 alive = g_vbits[img][c] & ~remv[c];
            int nk = 0;
            while (alive) {
                int b = __ffsll((long long)alive) - 1;
                skept[nk++] = i0 + b;
                alive &= ~smaskc[b];          // row has only j>i bits
                alive &= ~(1ull << b);
            }
            snk = nk;
        }
        __syncthreads();
        int nk = snk, kbase = skbase;
        // write kept boxes
        for (int kk = threadIdx.x; kk < nk; kk += blockDim.x) {
            int rank = kbase + kk;
            if (rank < POSTN) {
                int i = skept[kk];
                float* o = out + ((size_t)img * POSTN + rank) * 4;
                o[0] = g_sx1[img][i]; o[1] = g_sy1[img][i];
                o[2] = g_sx2[img][i]; o[3] = g_sy2[img][i];
            }
        }
        // parallel OR of kept rows into FUTURE remv words (w > c only)
        int nw = NWORDS - 1 - c;
        int total = nk * nw;
        for (int p = threadIdx.x; p < total; p += blockDim.x) {
            int kk = p / nw; int w = c + 1 + p - kk * nw;
            u64 m = g_mask[img][skept[kk]][w];
            if (m) atomicOr(&remv[w], m);
        }
        __syncthreads();
        if (threadIdx.x == 0) skbase = kbase + nk;
        __syncthreads();
    }
    __syncthreads();
    int tot = skbase; if (tot > POSTN) tot = POSTN;
    for (int idx = tot * 4 + threadIdx.x; idx < POSTN * 4; idx += blockDim.x)
        out[(size_t)img * POSTN * 4 + idx] = 0.0f;
}

// ================= host launcher =================
extern "C" void kernel_launch(void* const* d_in, const int* in_sizes, int n_in,
                              void* d_out, int out_size) {
    KArgs A;
    bool interleaved = (in_sizes[1] == 6291456);
    for (int i = 0; i < 5; i++) {
        A.obj[i] = (const float*)d_in[interleaved ? 2 * i : i];
        A.del[i] = (const float*)d_in[interleaved ? 2 * i + 1 : 5 + i];
    }
    A.anc = (const float*)d_in[10];
    float* out = (float*)d_out;

    cudaFuncSetAttribute(sortB_kernel, cudaFuncAttributeMaxDynamicSharedMemorySize, 65536);

    sel_kernel<<<40, 1024>>>(A);
    stage2_kernel<<<dim3(19, NIMG), 256>>>(A);
    sortB_kernel<<<NIMG, 1024, 65536>>>();
    stage3_kernel<<<dim3(19, NIMG), 256>>>();
    mask_kernel<<<dim3(NWORDS, NWORDS, NIMG), 64>>>();
    nms_scan_kernel<<<NIMG, 1024>>>(out);
}

// round 8
// speedup vs baseline: 1.5796x; 1.3862x over previous
#include <cuda_runtime.h>
#include <math.h>
#include <stdint.h>

#define NIMG   8
#define KSEL   4768
#define NWORDS 75          /* ceil(4768/64) */
#define POSTN  1000
#define CANDCAP 16384

typedef unsigned long long u64;
typedef unsigned int u32;

__device__ __constant__ int c_FEAT[5]   = {256, 128, 64, 32, 16};
__device__ __constant__ int c_KLVL[5]   = {1000, 1000, 1000, 1000, 768};
__device__ __constant__ int c_SELOFF[5] = {0, 1000, 2000, 3000, 4000};
__device__ __constant__ int c_LOFF[5]   = {0, 196608, 245760, 258048, 261120};

struct KArgs {
    const float* obj[5];
    const float* del[5];
    const float* anc;
};

// ------------- static device scratch (no allocation) -------------
__device__ u32    g_selIdx[NIMG][KSEL];        // concat-pos -> global anchor index
__device__ u64    g_cand[40][CANDCAP];         // sel candidate scratch
__device__ float4 g_px[NIMG][KSEL];            // pos-indexed clipped boxes
__device__ float  g_sx1[NIMG][KSEL], g_sy1[NIMG][KSEL], g_sx2[NIMG][KSEL], g_sy2[NIMG][KSEL];
__device__ float  g_ox1[NIMG][KSEL], g_oy1[NIMG][KSEL], g_ox2[NIMG][KSEL], g_oy2[NIMG][KSEL];
__device__ float  g_area[NIMG][KSEL];
__device__ unsigned char g_slvl[NIMG][KSEL];   // level per sorted rank
__device__ u64    g_vbits[NIMG][NWORDS];       // per-chunk valid bitmask (rank order)
__device__ u64    g_mask[NIMG][KSEL][NWORDS];  // suppression bit matrix (upper tri only)

// monotone float->uint key (ascending float == ascending uint)
__device__ __forceinline__ u32 fkey(float f) {
    u32 b = __float_as_uint(f);
    return (b & 0x80000000u) ? ~b : (b | 0x80000000u);
}

// ================= kernel 1: per-(img,level) exact top-k =================
__global__ __launch_bounds__(1024) void sel_kernel(KArgs A) {
    int img = blockIdx.x / 5, lvl = blockIdx.x % 5;
    const float* obj = A.obj[lvl];
    int F = c_FEAT[lvl]; int HW = F * F; int n = HW * 3; int k = c_KLVL[lvl];
    const float* base = obj + (size_t)img * 3 * HW;
    u64* cand = g_cand[blockIdx.x];

    __shared__ u32 hist[256];
    __shared__ u32 sh_prefix, sh_kr;
    __shared__ u64 buf[2048];
    __shared__ u32 cntG, cntE, cntC;

    // ---- pass 1: histogram of top-8 bits over full data ----
    for (int t = threadIdx.x; t < 256; t += blockDim.x) hist[t] = 0;
    if (threadIdx.x == 0) { cntC = 0; cntG = 0; cntE = 0; }
    __syncthreads();
    for (int t = threadIdx.x; t < n; t += blockDim.x)
        atomicAdd(&hist[fkey(base[t]) >> 24], 1u);
    __syncthreads();
    if (threadIdx.x == 0) {
        u32 kr = (u32)k, sum = 0; int d = 0;
        for (d = 255; d >= 0; d--) {
            u32 s2 = sum + hist[d];
            if (s2 >= kr) { sh_kr = kr - sum; break; }
            sum = s2;
        }
        sh_prefix = (u32)d << 24;
    }
    __syncthreads();
    u32 d1 = sh_prefix >> 24;

    // ---- pass 2: compact all candidates (top8 >= d1) into global scratch ----
    for (int t = threadIdx.x; t < n; t += blockDim.x) {
        u32 key = fkey(base[t]);
        if ((key >> 24) >= d1) {
            u32 s = atomicAdd(&cntC, 1u);
            if (s < CANDCAP) {
                int a = t / HW; int hw = t - a * HW;
                u32 local = (u32)hw * 3u + (u32)a;     // [H,W,A] flatten index
                cand[s] = ((u64)key << 32) | (u32)(~local);
            }
        }
    }
    __syncthreads();
    u32 m = cntC < CANDCAP ? cntC : CANDCAP;

    // ---- passes 3-5: radix select on the small candidate buffer ----
    for (int b = 2; b >= 0; b--) {
        for (int t = threadIdx.x; t < 256; t += blockDim.x) hist[t] = 0;
        __syncthreads();
        u32 pref = sh_prefix;
        u32 maskH = 0xFFFFFFFFu << (8 * (b + 1));
        for (int t = threadIdx.x; t < (int)m; t += blockDim.x) {
            u32 key = (u32)(cand[t] >> 32);
            if ((key & maskH) == (pref & maskH))
                atomicAdd(&hist[(key >> (8 * b)) & 255u], 1u);
        }
        __syncthreads();
        if (threadIdx.x == 0) {
            u32 kr = sh_kr, sum = 0; int d = 0;
            for (d = 255; d >= 0; d--) {
                u32 s2 = sum + hist[d];
                if (s2 >= kr) { sh_kr = kr - sum; break; }
                sum = s2;
            }
            sh_prefix = pref | ((u32)d << (8 * b));
        }
        __syncthreads();
    }
    u32 Kth = sh_prefix;

    // ---- compact G/E from candidate buffer ----
    for (int t = threadIdx.x; t < 2048; t += blockDim.x) buf[t] = 0ull;
    __syncthreads();
    for (int t = threadIdx.x; t < (int)m; t += blockDim.x) {
        u64 comp = cand[t];
        u32 key = (u32)(comp >> 32);
        if (key > Kth)       { u32 s = atomicAdd(&cntG, 1u); if (s < 1000u) buf[s] = comp; }
        else if (key == Kth) { u32 s = atomicAdd(&cntE, 1u); if (s < 1048u) buf[1000u + s] = comp; }
    }
    __syncthreads();

    // bitonic sort 2048 descending on (key desc, local asc)
    for (int kk = 2; kk <= 2048; kk <<= 1)
        for (int j = kk >> 1; j > 0; j >>= 1) {
            __syncthreads();
            for (int t = threadIdx.x; t < 2048; t += blockDim.x) {
                int ixj = t ^ j;
                if (ixj > t) {
                    u64 a = buf[t], bb = buf[ixj];
                    bool desc = ((t & kk) == 0);
                    if (desc ? (a < bb) : (a > bb)) { buf[t] = bb; buf[ixj] = a; }
                }
            }
        }
    __syncthreads();

    int seloff = c_SELOFF[lvl], loff = c_LOFF[lvl];
    for (int r = threadIdx.x; r < k; r += blockDim.x) {
        u32 local = ~(u32)buf[r];
        g_selIdx[img][seloff + r] = (u32)loff + local;
    }
}

// ================= kernel 2: fused decode + merge-rank + scatter =================
// Within each level, selected entries are already in descending composite order
// (logit desc, idx asc ties -> sigmoid non-increasing, ~pos tie-break). Global
// stable argsort(-s) == 5-way merge of these runs, invalids (score -1) trailing
// in pos order. Rank = own-level index + sum of strictly-greater counts in the
// other 4 sorted lists (binary search; composite keys are globally unique).
__global__ __launch_bounds__(1024) void rank_kernel(KArgs A) {
    int img = blockIdx.x;
    int tid = threadIdx.x;
    int lane = tid & 31, warp = tid >> 5;

    __shared__ u64 levKeys[KSEL];      // compacted valid keys, level-concatenated
    __shared__ u32 sh_wsum[32];
    __shared__ u32 sh_levStart[6];
    __shared__ u32 sh_carry, sh_total;

    for (int t = tid; t < NWORDS; t += 1024) g_vbits[img][t] = 0ull;

    // ---- phase A: decode all positions ----
    u64 key[5]; u32 gvp[5]; bool val[5];
    #pragma unroll
    for (int s = 0; s < 5; s++) {
        int p = s * 1024 + tid;
        key[s] = 0ull; val[s] = false;
        if (p < KSEL) {
            int lvl = p / 1000; if (lvl > 4) lvl = 4;
            u32 gidx = g_selIdx[img][p];
            int loff = c_LOFF[lvl]; int F = c_FEAT[lvl]; int HW = F * F;
            u32 local = gidx - (u32)loff;
            int a = (int)(local % 3u); int hw = (int)(local / 3u);
            int h = hw / F; int w = hw - h * F;

            float logit = A.obj[lvl][((size_t)img * 3 + a) * HW + hw];
            float score = __fdiv_rn(1.0f, __fadd_rn(1.0f, expf(-logit)));

            const float* dp = A.del[lvl] + ((size_t)img * 12 + a * 4) * HW + (size_t)h * F + w;
            float dx  = dp[0];
            float dy  = dp[(size_t)HW];
            float dwv = dp[2 * (size_t)HW];
            float dhv = dp[3 * (size_t)HW];
            const float* an = A.anc + 4 * (size_t)gidx;
            float ax1 = an[0], ay1 = an[1], ax2 = an[2], ay2 = an[3];
            float aw = __fsub_rn(ax2, ax1);
            float ah = __fsub_rn(ay2, ay1);
            float cx = __fadd_rn(ax1, __fmul_rn(0.5f, aw));
            float cy = __fadd_rn(ay1, __fmul_rn(0.5f, ah));
            const float CLIP = 4.135166556742356f;
            float dwc = fminf(dwv, CLIP);
            float dhc = fminf(dhv, CLIP);
            float pcx = __fadd_rn(__fmul_rn(dx, aw), cx);
            float pcy = __fadd_rn(__fmul_rn(dy, ah), cy);
            float pw  = __fmul_rn(expf(dwc), aw);
            float ph  = __fmul_rn(expf(dhc), ah);
            float x1 = __fsub_rn(pcx, __fmul_rn(0.5f, pw));
            float y1 = __fsub_rn(pcy, __fmul_rn(0.5f, ph));
            float x2 = __fadd_rn(pcx, __fmul_rn(0.5f, pw));
            float y2 = __fadd_rn(pcy, __fmul_rn(0.5f, ph));
            x1 = fminf(fmaxf(x1, 0.0f), 1024.0f);
            y1 = fminf(fmaxf(y1, 0.0f), 1024.0f);
            x2 = fminf(fmaxf(x2, 0.0f), 1024.0f);
            y2 = fminf(fmaxf(y2, 0.0f), 1024.0f);

            bool valid = (__fsub_rn(x2, x1) >= 1e-3f) && (__fsub_rn(y2, y1) >= 1e-3f);
            g_px[img][p] = make_float4(x1, y1, x2, y2);
            val[s] = valid;
            float sc = valid ? score : -1.0f;
            key[s] = ((u64)fkey(sc) << 32) | (u32)(~(u32)p);
        }
    }
    if (tid == 0) sh_carry = 0;

    // ---- phase B: block-wide exclusive scan of valid flags (pos order) ----
    #pragma unroll
    for (int s = 0; s < 5; s++) {
        int p = s * 1024 + tid;
        u32 bal = __ballot_sync(0xFFFFFFFFu, val[s]);
        u32 wpre = __popc(bal & ((1u << lane) - 1u));
        __syncthreads();                         // protect sh_wsum reuse
        if (lane == 0) sh_wsum[warp] = __popc(bal);
        __syncthreads();
        if (tid < 32) {
            u32 v = sh_wsum[tid];
            u32 x = v;
            #pragma unroll
            for (int o = 1; o < 32; o <<= 1) {
                u32 y = __shfl_up_sync(0xFFFFFFFFu, x, o);
                if (tid >= o) x += y;
            }
            sh_wsum[tid] = x - v;                // exclusive
            if (tid == 31) sh_total = x;         // inclusive total of slice
        }
        __syncthreads();
        gvp[s] = sh_carry + sh_wsum[warp] + wpre;
        if (p < KSEL && (p % 1000) == 0 && p < 5000) sh_levStart[p / 1000] = gvp[s];
        __syncthreads();
        if (tid == 0) sh_carry += sh_total;
    }
    __syncthreads();
    if (tid == 0) sh_levStart[5] = sh_carry;     // totalValid
    __syncthreads();

    // ---- phase C: compact valid keys (level-concatenated, descending) ----
    #pragma unroll
    for (int s = 0; s < 5; s++) {
        int p = s * 1024 + tid;
        if (p < KSEL && val[s]) levKeys[gvp[s]] = key[s];
    }
    __syncthreads();
    u32 totalValid = sh_levStart[5];

    // ---- phase D: rank + scatter ----
    #pragma unroll
    for (int s = 0; s < 5; s++) {
        int p = s * 1024 + tid;
        if (p >= KSEL) continue;
        int lvl = p / 1000; if (lvl > 4) lvl = 4;
        u32 r;
        if (val[s]) {
            r = gvp[s] - sh_levStart[lvl];       // index within own level
            #pragma unroll
            for (int l2 = 0; l2 < 5; l2++) {
                if (l2 == lvl) continue;
                u32 lo = sh_levStart[l2], hi = sh_levStart[l2 + 1];
                u32 st = lo;
                while (lo < hi) {
                    u32 mid = (lo + hi) >> 1;
                    if (levKeys[mid] > key[s]) lo = mid + 1; else hi = mid;
                }
                r += lo - st;
            }
        } else {
            r = totalValid + ((u32)p - gvp[s]);  // invalids trail in pos order
        }
        float4 b = g_px[img][p];
        g_sx1[img][r] = b.x; g_sy1[img][r] = b.y; g_sx2[img][r] = b.z; g_sy2[img][r] = b.w;
        float ofs = (float)lvl * 1025.0f;
        float ox1 = __fadd_rn(b.x, ofs), oy1 = __fadd_rn(b.y, ofs);
        float ox2 = __fadd_rn(b.z, ofs), oy2 = __fadd_rn(b.w, ofs);
        g_ox1[img][r] = ox1; g_oy1[img][r] = oy1; g_ox2[img][r] = ox2; g_oy2[img][r] = oy2;
        g_area[img][r] = __fmul_rn(__fsub_rn(ox2, ox1), __fsub_rn(oy2, oy1));
        g_slvl[img][r] = (unsigned char)lvl;
        if (val[s]) atomicOr(&g_vbits[img][r >> 6], 1ull << (r & 63));
    }
}

// ================= kernel 3: IoU suppression mask (upper tri, level-gated) =================
// Cross-level offset boxes have gap >= 1 => intersection exactly 0 => iou=0<=0.7:
// decision provably identical, so only same-level pairs need the IoU math.
__global__ __launch_bounds__(64) void mask_kernel() {
    int colb = blockIdx.x, rowb = blockIdx.y, img = blockIdx.z;
    if (colb < rowb) return;                 // lower-triangle words never read
    int tid = threadIdx.x;
    __shared__ float cx1[64], cy1[64], cx2[64], cy2[64], car[64];
    __shared__ u64 lvlbits[5];
    if (tid < 5) lvlbits[tid] = 0ull;
    __syncthreads();
    int j0 = colb * 64;
    int tj = j0 + tid;
    if (tj < KSEL) {
        cx1[tid] = g_ox1[img][tj]; cy1[tid] = g_oy1[img][tj];
        cx2[tid] = g_ox2[img][tj]; cy2[tid] = g_oy2[img][tj];
        car[tid] = g_area[img][tj];
        atomicOr(&lvlbits[g_slvl[img][tj]], 1ull << tid);
    }
    __syncthreads();
    int i = rowb * 64 + tid;
    if (i >= KSEL) return;
    int myl = (int)g_slvl[img][i];
    float ix1 = g_ox1[img][i], iy1 = g_oy1[img][i];
    float ix2 = g_ox2[img][i], iy2 = g_oy2[img][i];
    float ai = g_area[img][i];
    u64 candm = lvlbits[myl];
    if (rowb == colb) {
        int sh = i - j0;                      // 0..63: exclude j <= i
        u64 low = (sh == 63) ? ~0ull : ((1ull << (sh + 1)) - 1ull);
        candm &= ~low;
    }
    u64 word = 0ull;
    while (candm) {
        int jj = __ffsll((long long)candm) - 1;
        candm &= candm - 1ull;
        float ltx = fmaxf(ix1, cx1[jj]);
        float lty = fmaxf(iy1, cy1[jj]);
        float rbx = fminf(ix2, cx2[jj]);
        float rby = fminf(iy2, cy2[jj]);
        float w = fmaxf(__fsub_rn(rbx, ltx), 0.0f);
        float h = fmaxf(__fsub_rn(rby, lty), 0.0f);
        float inter = __fmul_rn(w, h);
        float den = __fadd_rn(__fsub_rn(__fadd_rn(ai, car[jj]), inter), 1e-9f);
        if (__fdiv_rn(inter, den) > 0.7f) word |= (1ull << jj);
    }
    g_mask[img][i][colb] = word;
}

// ================= kernel 4: greedy NMS scan (parallel remv update) =================
__global__ __launch_bounds__(1024) void nms_scan_kernel(float* __restrict__ out) {
    int img = blockIdx.x;
    __shared__ u64 remv[NWORDS];
    __shared__ u64 smaskc[64];
    __shared__ int skept[64];
    __shared__ int snk, skbase;
    for (int t = threadIdx.x; t < NWORDS; t += blockDim.x) remv[t] = 0ull;
    if (threadIdx.x == 0) { skbase = 0; snk = 0; }
    __syncthreads();

    for (int c = 0; c < NWORDS; c++) {
        if (skbase >= POSTN) break;          // uniform: shared + synced
        int i0 = c * 64;
        if (threadIdx.x < 64) {
            int i = i0 + threadIdx.x;
            smaskc[threadIdx.x] = (i < KSEL) ? g_mask[img][i][c] : 0ull;
        }
        __syncthreads();
        if (threadIdx.x == 0) {
            u64 alive = g_vbits[img][c] & ~remv[c];
            int nk = 0;
            while (alive) {
                int b = __ffsll((long long)alive) - 1;
                skept[nk++] = i0 + b;
                alive &= ~smaskc[b];          // row has only j>i bits
                alive &= ~(1ull << b);
            }
            snk = nk;
        }
        __syncthreads();
        int nk = snk, kbase = skbase;
        for (int kk = threadIdx.x; kk < nk; kk += blockDim.x) {
            int rank = kbase + kk;
            if (rank < POSTN) {
                int i = skept[kk];
                float* o = out + ((size_t)img * POSTN + rank) * 4;
                o[0] = g_sx1[img][i]; o[1] = g_sy1[img][i];
                o[2] = g_sx2[img][i]; o[3] = g_sy2[img][i];
            }
        }
        int nw = NWORDS - 1 - c;
        int total = nk * nw;
        for (int p = threadIdx.x; p < total; p += blockDim.x) {
            int kk = p / nw; int w = c + 1 + p - kk * nw;
            u64 m = g_mask[img][skept[kk]][w];
            if (m) atomicOr(&remv[w], m);
        }
        __syncthreads();
        if (threadIdx.x == 0) skbase = kbase + nk;
        __syncthreads();
    }
    __syncthreads();
    int tot = skbase; if (tot > POSTN) tot = POSTN;
    for (int idx = tot * 4 + threadIdx.x; idx < POSTN * 4; idx += blockDim.x)
        out[(size_t)img * POSTN * 4 + idx] = 0.0f;
}

// ================= host launcher =================
extern "C" void kernel_launch(void* const* d_in, const int* in_sizes, int n_in,
                              void* d_out, int out_size) {
    KArgs A;
    bool interleaved = (in_sizes[1] == 6291456);
    for (int i = 0; i < 5; i++) {
        A.obj[i] = (const float*)d_in[interleaved ? 2 * i : i];
        A.del[i] = (const float*)d_in[interleaved ? 2 * i + 1 : 5 + i];
    }
    A.anc = (const float*)d_in[10];
    float* out = (float*)d_out;

    sel_kernel<<<40, 1024>>>(A);
    rank_kernel<<<NIMG, 1024>>>(A);
    mask_kernel<<<dim3(NWORDS, NWORDS, NIMG), 64>>>();
    nms_scan_kernel<<<NIMG, 1024>>>(out);
}

// round 9
// speedup vs baseline: 1.6598x; 1.0507x over previous
#include <cuda_runtime.h>
#include <math.h>
#include <stdint.h>

#define NIMG   8
#define KSEL   4768
#define NWORDS 75          /* ceil(4768/64) */
#define POSTN  1000
#define CANDCAP 16384

typedef unsigned long long u64;
typedef unsigned int u32;

__device__ __constant__ int c_FEAT[5]   = {256, 128, 64, 32, 16};
__device__ __constant__ int c_KLVL[5]   = {1000, 1000, 1000, 1000, 768};
__device__ __constant__ int c_SELOFF[5] = {0, 1000, 2000, 3000, 4000};
__device__ __constant__ int c_LOFF[5]   = {0, 196608, 245760, 258048, 261120};

struct KArgs {
    const float* obj[5];
    const float* del[5];
    const float* anc;
};

// ------------- static device scratch (no allocation) -------------
__device__ u32    g_selIdx[NIMG][KSEL];        // concat-pos -> global anchor index
__device__ u64    g_cand[40][CANDCAP];         // sel candidate scratch
__device__ float4 g_px[NIMG][KSEL];            // pos-indexed clipped boxes
__device__ float  g_sx1[NIMG][KSEL], g_sy1[NIMG][KSEL], g_sx2[NIMG][KSEL], g_sy2[NIMG][KSEL];
__device__ float  g_ox1[NIMG][KSEL], g_oy1[NIMG][KSEL], g_ox2[NIMG][KSEL], g_oy2[NIMG][KSEL];
__device__ float  g_area[NIMG][KSEL];
__device__ unsigned char g_slvl[NIMG][KSEL];   // level per sorted rank
__device__ u64    g_vbits[NIMG][NWORDS];       // per-chunk valid bitmask (rank order)
__device__ u64    g_mask[NIMG][KSEL][NWORDS];  // suppression bit matrix (upper tri only)

// monotone float->uint key (ascending float == ascending uint)
__device__ __forceinline__ u32 fkey(float f) {
    u32 b = __float_as_uint(f);
    return (b & 0x80000000u) ? ~b : (b | 0x80000000u);
}

// ================= kernel 1: per-(img,level) exact top-k =================
__global__ __launch_bounds__(1024) void sel_kernel(KArgs A) {
    int img = blockIdx.x / 5, lvl = blockIdx.x % 5;
    const float* obj = A.obj[lvl];
    int F = c_FEAT[lvl]; int HW = F * F; int n = HW * 3; int k = c_KLVL[lvl];
    const float* base = obj + (size_t)img * 3 * HW;
    u64* cand = g_cand[blockIdx.x];

    __shared__ u32 hist[256];
    __shared__ u32 sh_prefix, sh_kr;
    __shared__ u64 buf[2048];
    __shared__ u32 cntG, cntE, cntC;

    // ---- pass 1: histogram of top-8 bits over full data ----
    for (int t = threadIdx.x; t < 256; t += blockDim.x) hist[t] = 0;
    if (threadIdx.x == 0) { cntC = 0; cntG = 0; cntE = 0; }
    __syncthreads();
    for (int t = threadIdx.x; t < n; t += blockDim.x)
        atomicAdd(&hist[fkey(base[t]) >> 24], 1u);
    __syncthreads();
    if (threadIdx.x == 0) {
        u32 kr = (u32)k, sum = 0; int d = 0;
        for (d = 255; d >= 0; d--) {
            u32 s2 = sum + hist[d];
            if (s2 >= kr) { sh_kr = kr - sum; break; }
            sum = s2;
        }
        sh_prefix = (u32)d << 24;
    }
    __syncthreads();
    u32 d1 = sh_prefix >> 24;

    // ---- pass 2: compact all candidates (top8 >= d1) into global scratch ----
    for (int t = threadIdx.x; t < n; t += blockDim.x) {
        u32 key = fkey(base[t]);
        if ((key >> 24) >= d1) {
            u32 s = atomicAdd(&cntC, 1u);
            if (s < CANDCAP) {
                int a = t / HW; int hw = t - a * HW;
                u32 local = (u32)hw * 3u + (u32)a;     // [H,W,A] flatten index
                cand[s] = ((u64)key << 32) | (u32)(~local);
            }
        }
    }
    __syncthreads();
    u32 m = cntC < CANDCAP ? cntC : CANDCAP;

    // ---- passes 3-5: radix select on the small candidate buffer ----
    for (int b = 2; b >= 0; b--) {
        for (int t = threadIdx.x; t < 256; t += blockDim.x) hist[t] = 0;
        __syncthreads();
        u32 pref = sh_prefix;
        u32 maskH = 0xFFFFFFFFu << (8 * (b + 1));
        for (int t = threadIdx.x; t < (int)m; t += blockDim.x) {
            u32 key = (u32)(cand[t] >> 32);
            if ((key & maskH) == (pref & maskH))
                atomicAdd(&hist[(key >> (8 * b)) & 255u], 1u);
        }
        __syncthreads();
        if (threadIdx.x == 0) {
            u32 kr = sh_kr, sum = 0; int d = 0;
            for (d = 255; d >= 0; d--) {
                u32 s2 = sum + hist[d];
                if (s2 >= kr) { sh_kr = kr - sum; break; }
                sum = s2;
            }
            sh_prefix = pref | ((u32)d << (8 * b));
        }
        __syncthreads();
    }
    u32 Kth = sh_prefix;

    // ---- compact G/E from candidate buffer ----
    for (int t = threadIdx.x; t < 2048; t += blockDim.x) buf[t] = 0ull;
    __syncthreads();
    for (int t = threadIdx.x; t < (int)m; t += blockDim.x) {
        u64 comp = cand[t];
        u32 key = (u32)(comp >> 32);
        if (key > Kth)       { u32 s = atomicAdd(&cntG, 1u); if (s < 1000u) buf[s] = comp; }
        else if (key == Kth) { u32 s = atomicAdd(&cntE, 1u); if (s < 1048u) buf[1000u + s] = comp; }
    }
    __syncthreads();

    // bitonic sort 2048 descending on (key desc, local asc)
    for (int kk = 2; kk <= 2048; kk <<= 1)
        for (int j = kk >> 1; j > 0; j >>= 1) {
            __syncthreads();
            for (int t = threadIdx.x; t < 2048; t += blockDim.x) {
                int ixj = t ^ j;
                if (ixj > t) {
                    u64 a = buf[t], bb = buf[ixj];
                    bool desc = ((t & kk) == 0);
                    if (desc ? (a < bb) : (a > bb)) { buf[t] = bb; buf[ixj] = a; }
                }
            }
        }
    __syncthreads();

    int seloff = c_SELOFF[lvl], loff = c_LOFF[lvl];
    for (int r = threadIdx.x; r < k; r += blockDim.x) {
        u32 local = ~(u32)buf[r];
        g_selIdx[img][seloff + r] = (u32)loff + local;
    }
}

// ================= kernel 2: fused decode + merge-rank + scatter =================
__global__ __launch_bounds__(1024) void rank_kernel(KArgs A) {
    int img = blockIdx.x;
    int tid = threadIdx.x;
    int lane = tid & 31, warp = tid >> 5;

    __shared__ u64 levKeys[KSEL];      // compacted valid keys, level-concatenated
    __shared__ u32 sh_wsum[32];
    __shared__ u32 sh_levStart[6];
    __shared__ u32 sh_carry, sh_total;

    for (int t = tid; t < NWORDS; t += 1024) g_vbits[img][t] = 0ull;

    // ---- phase A: decode all positions ----
    u64 key[5]; u32 gvp[5]; bool val[5];
    #pragma unroll
    for (int s = 0; s < 5; s++) {
        int p = s * 1024 + tid;
        key[s] = 0ull; val[s] = false;
        if (p < KSEL) {
            int lvl = p / 1000; if (lvl > 4) lvl = 4;
            u32 gidx = g_selIdx[img][p];
            int loff = c_LOFF[lvl]; int F = c_FEAT[lvl]; int HW = F * F;
            u32 local = gidx - (u32)loff;
            int a = (int)(local % 3u); int hw = (int)(local / 3u);
            int h = hw / F; int w = hw - h * F;

            float logit = A.obj[lvl][((size_t)img * 3 + a) * HW + hw];
            float score = __fdiv_rn(1.0f, __fadd_rn(1.0f, expf(-logit)));

            const float* dp = A.del[lvl] + ((size_t)img * 12 + a * 4) * HW + (size_t)h * F + w;
            float dx  = dp[0];
            float dy  = dp[(size_t)HW];
            float dwv = dp[2 * (size_t)HW];
            float dhv = dp[3 * (size_t)HW];
            const float* an = A.anc + 4 * (size_t)gidx;
            float ax1 = an[0], ay1 = an[1], ax2 = an[2], ay2 = an[3];
            float aw = __fsub_rn(ax2, ax1);
            float ah = __fsub_rn(ay2, ay1);
            float cx = __fadd_rn(ax1, __fmul_rn(0.5f, aw));
            float cy = __fadd_rn(ay1, __fmul_rn(0.5f, ah));
            const float CLIP = 4.135166556742356f;
            float dwc = fminf(dwv, CLIP);
            float dhc = fminf(dhv, CLIP);
            float pcx = __fadd_rn(__fmul_rn(dx, aw), cx);
            float pcy = __fadd_rn(__fmul_rn(dy, ah), cy);
            float pw  = __fmul_rn(expf(dwc), aw);
            float ph  = __fmul_rn(expf(dhc), ah);
            float x1 = __fsub_rn(pcx, __fmul_rn(0.5f, pw));
            float y1 = __fsub_rn(pcy, __fmul_rn(0.5f, ph));
            float x2 = __fadd_rn(pcx, __fmul_rn(0.5f, pw));
            float y2 = __fadd_rn(pcy, __fmul_rn(0.5f, ph));
            x1 = fminf(fmaxf(x1, 0.0f), 1024.0f);
            y1 = fminf(fmaxf(y1, 0.0f), 1024.0f);
            x2 = fminf(fmaxf(x2, 0.0f), 1024.0f);
            y2 = fminf(fmaxf(y2, 0.0f), 1024.0f);

            bool valid = (__fsub_rn(x2, x1) >= 1e-3f) && (__fsub_rn(y2, y1) >= 1e-3f);
            g_px[img][p] = make_float4(x1, y1, x2, y2);
            val[s] = valid;
            float sc = valid ? score : -1.0f;
            key[s] = ((u64)fkey(sc) << 32) | (u32)(~(u32)p);
        }
    }
    if (tid == 0) sh_carry = 0;

    // ---- phase B: block-wide exclusive scan of valid flags (pos order) ----
    #pragma unroll
    for (int s = 0; s < 5; s++) {
        int p = s * 1024 + tid;
        u32 bal = __ballot_sync(0xFFFFFFFFu, val[s]);
        u32 wpre = __popc(bal & ((1u << lane) - 1u));
        __syncthreads();                         // protect sh_wsum reuse
        if (lane == 0) sh_wsum[warp] = __popc(bal);
        __syncthreads();
        if (tid < 32) {
            u32 v = sh_wsum[tid];
            u32 x = v;
            #pragma unroll
            for (int o = 1; o < 32; o <<= 1) {
                u32 y = __shfl_up_sync(0xFFFFFFFFu, x, o);
                if (tid >= o) x += y;
            }
            sh_wsum[tid] = x - v;                // exclusive
            if (tid == 31) sh_total = x;         // inclusive total of slice
        }
        __syncthreads();
        gvp[s] = sh_carry + sh_wsum[warp] + wpre;
        if (p < KSEL && (p % 1000) == 0 && p < 5000) sh_levStart[p / 1000] = gvp[s];
        __syncthreads();
        if (tid == 0) sh_carry += sh_total;
    }
    __syncthreads();
    if (tid == 0) sh_levStart[5] = sh_carry;     // totalValid
    __syncthreads();

    // ---- phase C: compact valid keys (level-concatenated, descending) ----
    #pragma unroll
    for (int s = 0; s < 5; s++) {
        int p = s * 1024 + tid;
        if (p < KSEL && val[s]) levKeys[gvp[s]] = key[s];
    }
    __syncthreads();
    u32 totalValid = sh_levStart[5];

    // ---- phase D: rank + scatter ----
    #pragma unroll
    for (int s = 0; s < 5; s++) {
        int p = s * 1024 + tid;
        if (p >= KSEL) continue;
        int lvl = p / 1000; if (lvl > 4) lvl = 4;
        u32 r;
        if (val[s]) {
            r = gvp[s] - sh_levStart[lvl];       // index within own level
            #pragma unroll
            for (int l2 = 0; l2 < 5; l2++) {
                if (l2 == lvl) continue;
                u32 lo = sh_levStart[l2], hi = sh_levStart[l2 + 1];
                u32 st = lo;
                while (lo < hi) {
                    u32 mid = (lo + hi) >> 1;
                    if (levKeys[mid] > key[s]) lo = mid + 1; else hi = mid;
                }
                r += lo - st;
            }
        } else {
            r = totalValid + ((u32)p - gvp[s]);  // invalids trail in pos order
        }
        float4 b = g_px[img][p];
        g_sx1[img][r] = b.x; g_sy1[img][r] = b.y; g_sx2[img][r] = b.z; g_sy2[img][r] = b.w;
        float ofs = (float)lvl * 1025.0f;
        float ox1 = __fadd_rn(b.x, ofs), oy1 = __fadd_rn(b.y, ofs);
        float ox2 = __fadd_rn(b.z, ofs), oy2 = __fadd_rn(b.w, ofs);
        g_ox1[img][r] = ox1; g_oy1[img][r] = oy1; g_ox2[img][r] = ox2; g_oy2[img][r] = oy2;
        g_area[img][r] = __fmul_rn(__fsub_rn(ox2, ox1), __fsub_rn(oy2, oy1));
        g_slvl[img][r] = (unsigned char)lvl;
        if (val[s]) atomicOr(&g_vbits[img][r >> 6], 1ull << (r & 63));
    }
}

// ================= kernel 3: IoU suppression mask (upper tri, level-gated) =================
// 256 threads = 4 row-tiles sharing one column tile. Cross-level pairs provably
// iou==0 (offset gap >= 1) so only same-level pairs computed.
__global__ __launch_bounds__(256) void mask_kernel() {
    int colb = blockIdx.x, rowb4 = blockIdx.y, img = blockIdx.z;
    if (rowb4 * 4 > colb) return;            // whole block lower-triangle
    int tid = threadIdx.x;
    int sub = tid >> 6;                      // row-tile within block
    int lane64 = tid & 63;
    int rowb = rowb4 * 4 + sub;

    __shared__ float cx1[64], cy1[64], cx2[64], cy2[64], car[64];
    __shared__ u64 lvlbits[5];
    if (tid < 5) lvlbits[tid] = 0ull;
    __syncthreads();
    int j0 = colb * 64;
    if (tid < 64) {
        int tj = j0 + tid;
        if (tj < KSEL) {
            cx1[tid] = g_ox1[img][tj]; cy1[tid] = g_oy1[img][tj];
            cx2[tid] = g_ox2[img][tj]; cy2[tid] = g_oy2[img][tj];
            car[tid] = g_area[img][tj];
            atomicOr(&lvlbits[g_slvl[img][tj]], 1ull << tid);
        }
    }
    __syncthreads();
    if (rowb > colb) return;                 // this row-tile is lower triangle
    int i = rowb * 64 + lane64;
    if (i >= KSEL) return;
    int myl = (int)g_slvl[img][i];
    float ix1 = g_ox1[img][i], iy1 = g_oy1[img][i];
    float ix2 = g_ox2[img][i], iy2 = g_oy2[img][i];
    float ai = g_area[img][i];
    u64 candm = lvlbits[myl];
    if (rowb == colb) {
        int sh = i - j0;                     // exclude j <= i
        u64 low = (sh == 63) ? ~0ull : ((1ull << (sh + 1)) - 1ull);
        candm &= ~low;
    }
    u64 word = 0ull;
    while (candm) {
        int jj = __ffsll((long long)candm) - 1;
        candm &= candm - 1ull;
        float ltx = fmaxf(ix1, cx1[jj]);
        float lty = fmaxf(iy1, cy1[jj]);
        float rbx = fminf(ix2, cx2[jj]);
        float rby = fminf(iy2, cy2[jj]);
        float w = fmaxf(__fsub_rn(rbx, ltx), 0.0f);
        float h = fmaxf(__fsub_rn(rby, lty), 0.0f);
        float inter = __fmul_rn(w, h);
        float den = __fadd_rn(__fsub_rn(__fadd_rn(ai, car[jj]), inter), 1e-9f);
        if (__fdiv_rn(inter, den) > 0.7f) word |= (1ull << jj);
    }
    g_mask[img][i][colb] = word;
}

// ================= kernel 4: greedy NMS scan (lazy column evaluation) =================
// remv[w] is only read at chunk w, so compute the suppression word on demand:
// scol = OR over all previously-kept rows of mask[row][c]. ~18.5K independent
// loads/image instead of 55K eager ones, and only 3 small barriers per chunk.
__global__ __launch_bounds__(256) void nms_scan_kernel(float* __restrict__ out) {
    int img = blockIdx.x;
    int tid = threadIdx.x;
    __shared__ u64 smaskc[64];
    __shared__ u64 scol;
    __shared__ int skept[64];
    __shared__ int skeptAll[1152];
    __shared__ int snk, skbase;
    if (tid == 0) { skbase = 0; snk = 0; }
    __syncthreads();

    for (int c = 0; c < NWORDS; c++) {
        if (skbase >= POSTN) break;          // uniform (synced at loop tail)
        int i0 = c * 64;
        if (tid == 0) scol = 0ull;
        __syncthreads();
        if (tid < 64) {
            int i = i0 + tid;
            smaskc[tid] = (i < KSEL) ? g_mask[img][i][c] : 0ull;
        }
        int kb = skbase;
        u64 acc = 0ull;
        for (int k = tid; k < kb; k += 256)
            acc |= g_mask[img][skeptAll[k]][c];
        if (acc) atomicOr(&scol, acc);
        __syncthreads();
        if (tid == 0) {
            u64 alive = g_vbits[img][c] & ~scol;
            int nk = 0;
            while (alive) {
                int b = __ffsll((long long)alive) - 1;
                skept[nk] = i0 + b;
                skeptAll[kb + nk] = i0 + b;
                nk++;
                alive &= ~smaskc[b];          // row has only j>i bits
                alive &= ~(1ull << b);
            }
            snk = nk;
            skbase = kb + nk;
        }
        __syncthreads();
        int nk = snk;
        for (int kk = tid; kk < nk; kk += 256) {
            int rank = kb + kk;
            if (rank < POSTN) {
                int i = skept[kk];
                float* o = out + ((size_t)img * POSTN + rank) * 4;
                o[0] = g_sx1[img][i]; o[1] = g_sy1[img][i];
                o[2] = g_sx2[img][i]; o[3] = g_sy2[img][i];
            }
        }
        // no trailing barrier needed: next iteration's first barrier (after
        // scol reset) orders everything; skbase/skeptAll were written by tid0
        // before the post-scan barrier above.
    }
    __syncthreads();
    int tot = skbase; if (tot > POSTN) tot = POSTN;
    for (int idx = tot * 4 + tid; idx < POSTN * 4; idx += 256)
        out[(size_t)img * POSTN * 4 + idx] = 0.0f;
}

// ================= host launcher =================
extern "C" void kernel_launch(void* const* d_in, const int* in_sizes, int n_in,
                              void* d_out, int out_size) {
    KArgs A;
    bool interleaved = (in_sizes[1] == 6291456);
    for (int i = 0; i < 5; i++) {
        A.obj[i] = (const float*)d_in[interleaved ? 2 * i : i];
        A.del[i] = (const float*)d_in[interleaved ? 2 * i + 1 : 5 + i];
    }
    A.anc = (const float*)d_in[10];
    float* out = (float*)d_out;

    sel_kernel<<<40, 1024>>>(A);
    rank_kernel<<<NIMG, 1024>>>(A);
    mask_kernel<<<dim3(NWORDS, 19, NIMG), 256>>>();
    nms_scan_kernel<<<NIMG, 256>>>(out);
}